// round 6
// baseline (speedup 1.0000x reference)
#include <cuda_runtime.h>
#include <cuda_fp16.h>
#include <cstdint>

#define D_MODEL     2048
#define NUM_EXPERTS 64
#define TOP_K       4
#define TM          128              // tokens per CTA
#define KC          64               // K chunk
#define NCHUNK      (D_MODEL / KC)   // 32
#define N_TOKENS    16384
#define NBLK        (N_TOKENS / TM)  // 128
#define MAXREP      16384
#define GAP_EPS     1e-5f

// ---- smem layout: stride 144 B per row (72 halfs), conflict-free ldmatrix ----
#define RSTRIDE    144
#define A_HS       (TM * RSTRIDE)            // 18432 per (stage,half)
#define B_HS       (NUM_EXPERTS * RSTRIDE)   // 9216 per (stage,half)
#define OFF_A(st,h)  ((size_t)((st)*2 + (h)) * A_HS)          // 0..73728
#define OFF_B(st,h)  (73728 + (size_t)((st)*2 + (h)) * B_HS)  // ..110592
#define OFF_BIAS     110592
#define SM_TOTAL     110848
// epilogue L[128][65] fp32 = 33280 B reuses A region

// ---- device scratch ----
__device__ float  g_expert_partial[NBLK * NUM_EXPERTS];
__device__ __half g_ET_hi[NUM_EXPERTS * D_MODEL];   // E^T hi fp16, [n][k]
__device__ __half g_ET_lo[NUM_EXPERTS * D_MODEL];   // E^T lo fp16
__device__ int    g_count;
__device__ int    g_repair[MAXREP];

// ================= helpers ==================================================
__device__ __forceinline__ uint32_t smem_to_u32(const void* p) {
    uint32_t a;
    asm("{ .reg .u64 t; cvta.to.shared.u64 t, %1; cvt.u32.u64 %0, t; }" : "=r"(a) : "l"(p));
    return a;
}
#define CP_ASYNC16(dst_u32, src_ptr) \
    asm volatile("cp.async.cg.shared.global [%0], [%1], 16;" :: "r"(dst_u32), "l"(src_ptr))
#define CP_COMMIT() asm volatile("cp.async.commit_group;" ::: "memory")
#define CP_WAIT1()  asm volatile("cp.async.wait_group 1;" ::: "memory")
#define CP_WAIT0()  asm volatile("cp.async.wait_group 0;" ::: "memory")

#define LDSM4(r0, r1, r2, r3, addr) \
    asm volatile("ldmatrix.sync.aligned.m8n8.x4.shared.b16 {%0,%1,%2,%3}, [%4];" \
                 : "=r"(r0), "=r"(r1), "=r"(r2), "=r"(r3) : "r"(addr))

__device__ __forceinline__ void mma_f16(float* d, const uint32_t* a, uint32_t b0, uint32_t b1) {
    asm volatile(
        "mma.sync.aligned.m16n8k16.row.col.f32.f16.f16.f32 "
        "{%0,%1,%2,%3}, {%4,%5,%6,%7}, {%8,%9}, {%0,%1,%2,%3};"
        : "+f"(d[0]), "+f"(d[1]), "+f"(d[2]), "+f"(d[3])
        : "r"(a[0]), "r"(a[1]), "r"(a[2]), "r"(a[3]), "r"(b0), "r"(b1));
}

// ================= prep: E[2048][64] -> E^T fp16 hi/lo [n][k]; zero count ===
__global__ void prep_E(const float* __restrict__ E) {
    __shared__ float t[64][65];
    const int tid = threadIdx.x;
    const int k0 = blockIdx.x * 64;
    if (blockIdx.x == 0 && tid == 0) g_count = 0;
#pragma unroll
    for (int i = 0; i < 16; i++) {
        int idx = tid + i * 256;
        int r = idx >> 6, c = idx & 63;
        t[r][c] = E[(size_t)(k0 + r) * NUM_EXPERTS + c];
    }
    __syncthreads();
#pragma unroll
    for (int i = 0; i < 16; i++) {
        int idx = tid + i * 256;
        int n = idx >> 6, kk = idx & 63;
        float v = t[kk][n];
        __half h = __float2half_rn(v);
        __half l = __float2half_rn(v - __half2float(h));
        g_ET_hi[(size_t)n * D_MODEL + k0 + kk] = h;
        g_ET_lo[(size_t)n * D_MODEL + k0 + kk] = l;
    }
}

// ================= main router: fp16-split legacy HMMA ======================
__global__ void __launch_bounds__(256) router_kernel(
    const float* __restrict__ u, const float* __restrict__ bias,
    float* __restrict__ out_idx, float* __restrict__ out_val,
    float* __restrict__ out_scores)
{
    extern __shared__ char smem[];
    const uint32_t sb = smem_to_u32(smem);
    const int tid = threadIdx.x, wid = tid >> 5, lid = tid & 31;
    const int tokBase = blockIdx.x * TM;

    if (tid < NUM_EXPERTS) ((float*)(smem + OFF_BIAS))[tid] = bias[tid];

    // ---- A: LDG fp32 -> regs (per chunk: 4 toks x 8 k's per thread) ----
    const int atok = tid >> 3;          // 0..31 (+32*i)
    const int akseg = tid & 7;          // 8-half segment
    float4 vbuf[4][2];
    auto ldgA = [&](int c) {
        const int k0 = c * KC;
#pragma unroll
        for (int i = 0; i < 4; i++) {
            const float* src = u + (size_t)(tokBase + atok + 32 * i) * D_MODEL + k0 + akseg * 8;
            vbuf[i][0] = *reinterpret_cast<const float4*>(src);
            vbuf[i][1] = *reinterpret_cast<const float4*>(src + 4);
        }
    };
    auto stsA = [&](int c) {
        const int st = c & 1;
#pragma unroll
        for (int i = 0; i < 4; i++) {
            const int tok = atok + 32 * i;
            uint32_t hw[4], lw[4];
#pragma unroll
            for (int j = 0; j < 2; j++) {
                float4 v = vbuf[i][j];
                __half2 h0 = __float22half2_rn(make_float2(v.x, v.y));
                __half2 h1 = __float22half2_rn(make_float2(v.z, v.w));
                float2 f0 = __half22float2(h0), f1 = __half22float2(h1);
                __half2 l0 = __float22half2_rn(make_float2(v.x - f0.x, v.y - f0.y));
                __half2 l1 = __float22half2_rn(make_float2(v.z - f1.x, v.w - f1.y));
                hw[j * 2]     = *reinterpret_cast<uint32_t*>(&h0);
                hw[j * 2 + 1] = *reinterpret_cast<uint32_t*>(&h1);
                lw[j * 2]     = *reinterpret_cast<uint32_t*>(&l0);
                lw[j * 2 + 1] = *reinterpret_cast<uint32_t*>(&l1);
            }
            const uint32_t off = (uint32_t)(tok * RSTRIDE + akseg * 16);
            *reinterpret_cast<uint4*>(smem + OFF_A(st, 0) + off) = make_uint4(hw[0], hw[1], hw[2], hw[3]);
            *reinterpret_cast<uint4*>(smem + OFF_A(st, 1) + off) = make_uint4(lw[0], lw[1], lw[2], lw[3]);
        }
    };
    auto cpB = [&](int c) {
        const int st = c & 1;
        const int k0 = c * KC;
#pragma unroll
        for (int i = 0; i < 4; i++) {
            int q = tid + i * 256;           // 0..1023
            int h = q >> 9, n = (q >> 3) & 63, j = q & 7;
            const __half* src = (h ? g_ET_lo : g_ET_hi) + (size_t)n * D_MODEL + k0 + j * 8;
            CP_ASYNC16(sb + (uint32_t)(OFF_B(st, h) + n * RSTRIDE + j * 16), src);
        }
        CP_COMMIT();
    };

    float acc[8][4];
#pragma unroll
    for (int t = 0; t < 8; t++)
#pragma unroll
        for (int j = 0; j < 4; j++) acc[t][j] = 0.f;

    // fragment lane addressing
    const uint32_t a_row = (uint32_t)(wid * 16 + (lid & 15));
    const uint32_t a_kadd = (uint32_t)((lid >> 4) << 3);          // 0 or 8 halfs
    const uint32_t b_n = (uint32_t)((lid & 7) + ((lid >> 4) << 3));  // + nb
    const uint32_t b_kadd = (uint32_t)(((lid >> 3) & 1) << 3);

    // prologue
    ldgA(0); stsA(0); cpB(0);
    ldgA(1); stsA(1); cpB(1);
    ldgA(2);
    CP_WAIT1();
    __syncthreads();

    for (int c = 0; c < NCHUNK; c++) {
        const int st = c & 1;
        const uint32_t ah_base = sb + (uint32_t)OFF_A(st, 0) + a_row * RSTRIDE + a_kadd * 2;
        const uint32_t al_base = sb + (uint32_t)OFF_A(st, 1) + a_row * RSTRIDE + a_kadd * 2;
        const uint32_t bh_base = sb + (uint32_t)OFF_B(st, 0) + b_n * RSTRIDE + b_kadd * 2;
        const uint32_t bl_base = sb + (uint32_t)OFF_B(st, 1) + b_n * RSTRIDE + b_kadd * 2;

#pragma unroll
        for (int kq = 0; kq < 4; kq++) {
            const uint32_t kb = kq * 32;   // 16 halfs = 32 bytes
            uint32_t ah[4], al[4];
            LDSM4(ah[0], ah[1], ah[2], ah[3], ah_base + kb);
            LDSM4(al[0], al[1], al[2], al[3], al_base + kb);
#pragma unroll
            for (int nbq = 0; nbq < 4; nbq++) {
                const uint32_t nb = nbq * 16 * RSTRIDE;
                uint32_t bh[4], bl[4];
                LDSM4(bh[0], bh[1], bh[2], bh[3], bh_base + nb + kb);
                LDSM4(bl[0], bl[1], bl[2], bl[3], bl_base + nb + kb);
                float* d0 = acc[nbq * 2];
                float* d1 = acc[nbq * 2 + 1];
                mma_f16(d0, ah, bh[0], bh[1]);
                mma_f16(d1, ah, bh[2], bh[3]);
                mma_f16(d0, ah, bl[0], bl[1]);
                mma_f16(d1, ah, bl[2], bl[3]);
                mma_f16(d0, al, bh[0], bh[1]);
                mma_f16(d1, al, bh[2], bh[3]);
            }
        }
        __syncthreads();
        if (c + 2 < NCHUNK) { stsA(c + 2); cpB(c + 2); }
        if (c + 3 < NCHUNK) ldgA(c + 3);
        if (c + 2 < NCHUNK) CP_WAIT1(); else CP_WAIT0();
        __syncthreads();
    }

    // ---- epilogue: C frags -> L[128][65] ----
    float* L = (float*)smem;    // 33280 B < A region
    {
        const int gr = lid >> 2, cc = (lid & 3) * 2;
#pragma unroll
        for (int t = 0; t < 8; t++) {
            const int col = t * 8 + cc;
            const int r0 = wid * 16 + gr;
            L[r0 * 65 + col]           = acc[t][0];
            L[r0 * 65 + col + 1]       = acc[t][1];
            L[(r0 + 8) * 65 + col]     = acc[t][2];
            L[(r0 + 8) * 65 + col + 1] = acc[t][3];
        }
    }
    __syncthreads();

    const float* biasS = (const float*)(smem + OFF_BIAS);
    if (tid < TM) {
        const int t = tid;
        float p[64];
        float mx = -1e30f;
#pragma unroll
        for (int e = 0; e < 64; e++) { p[e] = L[t * 65 + e] + biasS[e]; mx = fmaxf(mx, p[e]); }
        float s = 0.f;
#pragma unroll
        for (int e = 0; e < 64; e++) { p[e] = expf(p[e] - mx); s += p[e]; }
        const float inv = 1.f / s;
#pragma unroll
        for (int e = 0; e < 64; e++) p[e] *= inv;

        const int gtok = tokBase + t;
        unsigned long long chosen = 0ull;
        float tv[5]; int tix[5];
#pragma unroll
        for (int r = 0; r < 5; r++) {
            float bv = -1.f; int bi = 0;
#pragma unroll
            for (int e = 0; e < 64; e++) {
                bool skip = (chosen >> e) & 1ull;
                if (!skip && p[e] > bv) { bv = p[e]; bi = e; }  // strict >: lowest idx ties
            }
            chosen |= 1ull << bi;
            tv[r] = bv; tix[r] = bi;
        }
#pragma unroll
        for (int r = 0; r < TOP_K; r++) {
            out_idx[(size_t)gtok * TOP_K + r] = (float)tix[r];
            out_val[(size_t)gtok * TOP_K + r] = tv[r];
        }
        float ming = tv[0] - tv[1];
        ming = fminf(ming, tv[1] - tv[2]);
        ming = fminf(ming, tv[2] - tv[3]);
        ming = fminf(ming, tv[3] - tv[4]);
        if (ming < GAP_EPS) {
            int pos = atomicAdd(&g_count, 1);
            if (pos < MAXREP) g_repair[pos] = gtok;
        }
#pragma unroll
        for (int e = 0; e < 64; e++) L[t * 65 + e] = p[e];
    }
    __syncthreads();

    for (int i = tid; i < TM * NUM_EXPERTS; i += 256) {
        int t = i >> 6, e = i & 63;
        out_scores[(size_t)(tokBase + t) * NUM_EXPERTS + e] = L[t * 65 + e];
    }
    if (tid < NUM_EXPERTS) {
        float s = 0.f;
#pragma unroll 8
        for (int t = 0; t < TM; t++) s += L[t * 65 + tid];
        g_expert_partial[(size_t)blockIdx.x * NUM_EXPERTS + tid] = s;
    }
}

// ================= exact repair: sequential fp32 chain ======================
__global__ void __launch_bounds__(64) repair_kernel(
    const float* __restrict__ u, const float* __restrict__ E,
    const float* __restrict__ bias,
    float* __restrict__ out_idx, float* __restrict__ out_val,
    float* __restrict__ out_scores)
{
    __shared__ float P[64];
    const int e = threadIdx.x;
    int nrep = g_count; if (nrep > MAXREP) nrep = MAXREP;

    for (int item = blockIdx.x; item < nrep; item += gridDim.x) {
        const int tok = g_repair[item];
        const float* ur = u + (size_t)tok * D_MODEL;
        float acc = 0.f;
#pragma unroll 8
        for (int k = 0; k < D_MODEL; k++)
            acc = fmaf(ur[k], E[(size_t)k * NUM_EXPERTS + e], acc);
        P[e] = acc + bias[e];
        __syncthreads();

        if (e == 0) {
            float p[64];
            float mx = -1e30f;
#pragma unroll
            for (int i = 0; i < 64; i++) { p[i] = P[i]; mx = fmaxf(mx, p[i]); }
            float s = 0.f;
#pragma unroll
            for (int i = 0; i < 64; i++) { p[i] = expf(p[i] - mx); s += p[i]; }
            const float inv = 1.f / s;
#pragma unroll
            for (int i = 0; i < 64; i++) p[i] *= inv;
#pragma unroll
            for (int i = 0; i < 64; i++) P[i] = p[i];

            unsigned long long chosen = 0ull;
#pragma unroll
            for (int r = 0; r < TOP_K; r++) {
                float bv = -1.f; int bi = 0;
#pragma unroll
                for (int i = 0; i < 64; i++) {
                    bool skip = (chosen >> i) & 1ull;
                    if (!skip && p[i] > bv) { bv = p[i]; bi = i; }
                }
                chosen |= 1ull << bi;
                out_idx[(size_t)tok * TOP_K + r] = (float)bi;
                out_val[(size_t)tok * TOP_K + r] = bv;
            }
        }
        __syncthreads();
        out_scores[(size_t)tok * NUM_EXPERTS + e] = P[e];
        __syncthreads();
    }
}

// ================= aux loss reduction =======================================
__global__ void aux_kernel(float* __restrict__ out_aux) {
    __shared__ float red[64][17];
    __shared__ float sq[64];
    const int tid = threadIdx.x;           // 1024 threads
    const int e = tid >> 4, j = tid & 15;
    float s = 0.f;
#pragma unroll
    for (int i = 0; i < 8; i++)
        s += g_expert_partial[(size_t)(j + 16 * i) * NUM_EXPERTS + e];
    red[e][j] = s;
    __syncthreads();
    if (tid < 64) {
        float t = 0.f;
#pragma unroll
        for (int k = 0; k < 16; k++) t += red[tid][k];
        float m = t * (1.f / (float)N_TOKENS);
        sq[tid] = m * m;
    }
    __syncthreads();
    if (tid == 0) {
        float a = 0.f;
#pragma unroll
        for (int k = 0; k < 64; k++) a += sq[k];
        out_aux[0] = a * (float)NUM_EXPERTS;
    }
}

// ================= launch ===================================================
extern "C" void kernel_launch(void* const* d_in, const int* in_sizes, int n_in,
                              void* d_out, int out_size)
{
    const float* u    = (const float*)d_in[0];
    const float* E    = (const float*)d_in[1];
    const float* bias = (const float*)d_in[2];

    float* out        = (float*)d_out;
    float* out_idx    = out;
    float* out_val    = out_idx + (size_t)N_TOKENS * TOP_K;
    float* out_scores = out_val + (size_t)N_TOKENS * TOP_K;
    float* out_aux    = out_scores + (size_t)N_TOKENS * NUM_EXPERTS;

    cudaFuncSetAttribute(router_kernel, cudaFuncAttributeMaxDynamicSharedMemorySize, SM_TOTAL);

    prep_E<<<D_MODEL / 64, 256>>>(E);
    router_kernel<<<NBLK, 256, SM_TOTAL>>>(u, bias, out_idx, out_val, out_scores);
    repair_kernel<<<256, 64>>>(u, E, bias, out_idx, out_val, out_scores);
    aux_kernel<<<1, 1024>>>(out_aux);
}

// round 9
// speedup vs baseline: 1.1752x; 1.1752x over previous
#include <cuda_runtime.h>
#include <cstdint>

#define D_MODEL     2048
#define NUM_EXPERTS 64
#define TOP_K       4
#define TM          16               // tokens per CTA
#define KC          64               // K chunk
#define NCHUNK      (D_MODEL / KC)   // 32
#define N_TOKENS    16384
#define NBLK        (N_TOKENS / TM)  // 1024

// smem word strides
#define AW          68               // words per token row (272B, conflict-free)
#define A_STAGE_B   (TM * AW * 4)    // 4352 B
#define B_STAGE_B   (KC * 256)       // 16384 B (raw E rows: 64 floats = 256B)

__device__ float g_expert_partial[NBLK * NUM_EXPERTS];
__device__ int   g_done;             // zero-init; reset by last CTA each run

__device__ __forceinline__ uint32_t smem_to_u32(const void* p) {
    uint32_t a;
    asm("{ .reg .u64 t; cvta.to.shared.u64 t, %1; cvt.u32.u64 %0, t; }" : "=r"(a) : "l"(p));
    return a;
}
#define CP_ASYNC16(dst_u32, src_ptr) \
    asm volatile("cp.async.cg.shared.global [%0], [%1], 16;" :: "r"(dst_u32), "l"(src_ptr))
#define CP_COMMIT() asm volatile("cp.async.commit_group;" ::: "memory")
#define CP_WAIT1()  asm volatile("cp.async.wait_group 1;" ::: "memory")
#define CP_WAIT0()  asm volatile("cp.async.wait_group 0;" ::: "memory")

__device__ __forceinline__ void fma2(unsigned long long& d, unsigned long long a, unsigned long long b) {
    asm("fma.rn.f32x2 %0, %1, %2, %0;" : "+l"(d) : "l"(a), "l"(b));
}
__device__ __forceinline__ unsigned long long dup2(float x) {
    unsigned long long r;
    uint32_t xb = __float_as_uint(x);
    asm("mov.b64 %0, {%1, %1};" : "=l"(r) : "r"(xb));
    return r;
}
__device__ __forceinline__ void unpack2(unsigned long long v, float& lo, float& hi) {
    uint32_t l, h;
    asm("mov.b64 {%0, %1}, %2;" : "=r"(l), "=r"(h) : "l"(v));
    lo = __uint_as_float(l); hi = __uint_as_float(h);
}

__global__ void __launch_bounds__(128) void_guard(); // fwd decl pacifier (unused)

__global__ void __launch_bounds__(128) router_kernel(
    const float* __restrict__ u, const float* __restrict__ E,
    const float* __restrict__ bias,
    float* __restrict__ out_idx, float* __restrict__ out_val,
    float* __restrict__ out_scores, float* __restrict__ out_aux)
{
    __shared__ __align__(16) char sA[2 * A_STAGE_B];      // 8704 B (also reused as L[16][65])
    __shared__ __align__(16) char sB[2 * B_STAGE_B];      // 32768 B
    __shared__ float biasS[NUM_EXPERTS];
    __shared__ float redA[2][NUM_EXPERTS];
    __shared__ float sq[NUM_EXPERTS];
    __shared__ int   lastFlag;

    const uint32_t sbA = smem_to_u32(sA);
    const uint32_t sbB = smem_to_u32(sB);
    const int tid = threadIdx.x, lid = tid & 31, wid = tid >> 5;
    const int tg = lid & 7;              // token slot: tokens tg, tg+8
    const int pg = (lid >> 3) & 3;       // pair slot within warp
    const int tokBase = blockIdx.x * TM;

    if (tid < NUM_EXPERTS) biasS[tid] = bias[tid];

    auto issue = [&](int c) {
        const int st = c & 1;
        const int k0 = c * KC;
        const uint32_t ab = sbA + st * A_STAGE_B;
        const uint32_t bb = sbB + st * B_STAGE_B;
        // A: 16 rows x 256B = 256 16B-units, 2 per thread
#pragma unroll
        for (int i = 0; i < 2; i++) {
            int unit = tid + 128 * i;
            int row = unit >> 4, off = unit & 15;
            CP_ASYNC16(ab + (uint32_t)(row * (AW * 4) + off * 16),
                       u + (size_t)(tokBase + row) * D_MODEL + k0 + off * 4);
        }
        // B: raw E rows k0..k0+63, 64 x 256B = 1024 units, 8 per thread
#pragma unroll
        for (int i = 0; i < 8; i++) {
            int unit = tid + 128 * i;
            int kr = unit >> 4, off = unit & 15;
            CP_ASYNC16(bb + (uint32_t)(kr * 256 + off * 16),
                       E + (size_t)(k0 + kr) * NUM_EXPERTS + off * 4);
        }
        CP_COMMIT();
    };

    unsigned long long a00 = 0ull, a01 = 0ull, a10 = 0ull, a11 = 0ull;
    const int p0 = wid * 8 + pg;         // pairs p0, p0+4 -> experts 2p0,2p0+1, 2p0+8,2p0+9

    issue(0);
    issue(1);

    for (int c = 0; c < NCHUNK; c++) {
        if (c < NCHUNK - 1) CP_WAIT1(); else CP_WAIT0();
        __syncthreads();

        const int st = c & 1;
        const float* as = (const float*)(sA + st * A_STAGE_B);
        const unsigned long long* bs = (const unsigned long long*)(sB + st * B_STAGE_B);

#pragma unroll 16
        for (int k = 0; k < KC; k++) {
            unsigned long long av0 = dup2(as[tg * AW + k]);
            unsigned long long av1 = dup2(as[(tg + 8) * AW + k]);
            unsigned long long bv0 = bs[k * 32 + p0];
            unsigned long long bv1 = bs[k * 32 + p0 + 4];
            fma2(a00, av0, bv0);
            fma2(a01, av0, bv1);
            fma2(a10, av1, bv0);
            fma2(a11, av1, bv1);
        }
        __syncthreads();
        if (c + 2 < NCHUNK) issue(c + 2);
    }

    // ---- epilogue: acc -> L[16][65] (reuse A region) ----
    // pair p0  -> experts 2*p0, 2*p0+1 ; pair p0+4 -> experts 2*p0+8, 2*p0+9
    float* L = (float*)sA;
    {
        const int e0 = 2 * p0;
        float lo, hi;
        unpack2(a00, lo, hi); L[tg * 65 + e0] = lo;          L[tg * 65 + e0 + 1] = hi;
        unpack2(a01, lo, hi); L[tg * 65 + e0 + 8] = lo;      L[tg * 65 + e0 + 9] = hi;
        unpack2(a10, lo, hi); L[(tg + 8) * 65 + e0] = lo;    L[(tg + 8) * 65 + e0 + 1] = hi;
        unpack2(a11, lo, hi); L[(tg + 8) * 65 + e0 + 8] = lo; L[(tg + 8) * 65 + e0 + 9] = hi;
    }
    __syncthreads();

    if (tid < TM) {
        const int t = tid;
        float p[64];
        float mx = -1e30f;
#pragma unroll
        for (int e = 0; e < 64; e++) { p[e] = L[t * 65 + e] + biasS[e]; mx = fmaxf(mx, p[e]); }
        float s = 0.f;
#pragma unroll
        for (int e = 0; e < 64; e++) { p[e] = expf(p[e] - mx); s += p[e]; }
        const float inv = 1.f / s;
#pragma unroll
        for (int e = 0; e < 64; e++) p[e] *= inv;

        const int gtok = tokBase + t;
        unsigned long long chosen = 0ull;
#pragma unroll
        for (int r = 0; r < TOP_K; r++) {
            float bv = -1.f; int bi = 0;
#pragma unroll
            for (int e = 0; e < 64; e++) {
                bool skip = (chosen >> e) & 1ull;
                if (!skip && p[e] > bv) { bv = p[e]; bi = e; }  // strict >: lowest idx ties
            }
            chosen |= 1ull << bi;
            out_idx[(size_t)gtok * TOP_K + r] = (float)bi;
            out_val[(size_t)gtok * TOP_K + r] = bv;
        }
#pragma unroll
        for (int e = 0; e < 64; e++) L[t * 65 + e] = p[e];
    }
    __syncthreads();

    // coalesced scores writeback: 1024 floats
#pragma unroll
    for (int i = 0; i < 8; i++) {
        int idx = tid + i * 128;
        int t = idx >> 6, e = idx & 63;
        out_scores[(size_t)(tokBase + t) * NUM_EXPERTS + e] = L[t * 65 + e];
    }
    // deterministic per-block expert sums
    if (tid < NUM_EXPERTS) {
        float s = 0.f;
#pragma unroll
        for (int t = 0; t < TM; t++) s += L[t * 65 + tid];
        g_expert_partial[(size_t)blockIdx.x * NUM_EXPERTS + tid] = s;
    }

    // ---- elected-last-CTA aux reduction (deterministic fixed-order sums) ----
    __threadfence();
    if (tid == 0) lastFlag = (atomicAdd(&g_done, 1) == NBLK - 1) ? 1 : 0;
    __syncthreads();
    if (lastFlag) {
        const int e = tid & 63, h = tid >> 6;          // 128 threads: 2 halves x 64 experts
        float s = 0.f;
        const int b0 = h * (NBLK / 2);
#pragma unroll 8
        for (int b = 0; b < NBLK / 2; b++)
            s += g_expert_partial[(size_t)(b0 + b) * NUM_EXPERTS + e];
        redA[h][e] = s;
        __syncthreads();
        if (tid < 64) {
            float m = (redA[0][tid] + redA[1][tid]) * (1.f / (float)N_TOKENS);
            sq[tid] = m * m;
        }
        __syncthreads();
        if (tid == 0) {
            float a = 0.f;
#pragma unroll
            for (int k = 0; k < 64; k++) a += sq[k];
            out_aux[0] = a * (float)NUM_EXPERTS;
            g_done = 0;                                // reset for next replay
        }
    }
}

extern "C" void kernel_launch(void* const* d_in, const int* in_sizes, int n_in,
                              void* d_out, int out_size)
{
    const float* u    = (const float*)d_in[0];
    const float* E    = (const float*)d_in[1];
    const float* bias = (const float*)d_in[2];

    float* out        = (float*)d_out;
    float* out_idx    = out;
    float* out_val    = out_idx + (size_t)N_TOKENS * TOP_K;
    float* out_scores = out_val + (size_t)N_TOKENS * TOP_K;
    float* out_aux    = out_scores + (size_t)N_TOKENS * NUM_EXPERTS;

    router_kernel<<<NBLK, 128>>>(u, E, bias, out_idx, out_val, out_scores, out_aux);
}

// round 10
// speedup vs baseline: 1.4537x; 1.2369x over previous
#include <cuda_runtime.h>
#include <cstdint>

#define D_MODEL     2048
#define NUM_EXPERTS 64
#define TOP_K       4
#define TM          64               // tokens per CTA
#define KC          16               // K chunk
#define NCHUNK      (D_MODEL / KC)   // 128
#define N_TOKENS    16384
#define NBLK        (N_TOKENS / TM)  // 256

#define AWW         20               // A row stride words (16 floats + 4 pad; 80B)
#define A_STAGE_B   (TM * AWW * 4)   // 5120 B
#define BWU         36               // B row stride ULL (64 floats + pad; 288B)
#define B_STAGE_B   (KC * BWU * 8)   // 4608 B
#define SBUF_BYTES  (2 * A_STAGE_B + 2 * B_STAGE_B)   // 19456
#define B_OFF       (2 * A_STAGE_B)                    // 10240

__device__ float g_expert_partial[NBLK * NUM_EXPERTS];
__device__ int   g_done;             // zero-init; reset by last CTA each run

__device__ __forceinline__ uint32_t smem_to_u32(const void* p) {
    uint32_t a;
    asm("{ .reg .u64 t; cvta.to.shared.u64 t, %1; cvt.u32.u64 %0, t; }" : "=r"(a) : "l"(p));
    return a;
}
#define CP_ASYNC16(dst_u32, src_ptr) \
    asm volatile("cp.async.cg.shared.global [%0], [%1], 16;" :: "r"(dst_u32), "l"(src_ptr))
#define CP_COMMIT() asm volatile("cp.async.commit_group;" ::: "memory")
#define CP_WAIT1()  asm volatile("cp.async.wait_group 1;" ::: "memory")
#define CP_WAIT0()  asm volatile("cp.async.wait_group 0;" ::: "memory")

__device__ __forceinline__ void fma2(unsigned long long& d, unsigned long long a, unsigned long long b) {
    asm("fma.rn.f32x2 %0, %1, %2, %0;" : "+l"(d) : "l"(a), "l"(b));
}
__device__ __forceinline__ unsigned long long dup2(float x) {
    unsigned long long r;
    uint32_t xb = __float_as_uint(x);
    asm("mov.b64 %0, {%1, %1};" : "=l"(r) : "r"(xb));
    return r;
}
__device__ __forceinline__ void unpack2(unsigned long long v, float& lo, float& hi) {
    uint32_t l, h;
    asm("mov.b64 {%0, %1}, %2;" : "=r"(l), "=r"(h) : "l"(v));
    lo = __uint_as_float(l); hi = __uint_as_float(h);
}

__global__ void __launch_bounds__(128, 4) router_kernel(
    const float* __restrict__ u, const float* __restrict__ E,
    const float* __restrict__ bias,
    float* __restrict__ out_idx, float* __restrict__ out_val,
    float* __restrict__ out_scores, float* __restrict__ out_aux)
{
    __shared__ __align__(16) char sbuf[SBUF_BYTES];   // A stages [0,10240), B stages [10240,19456)
    __shared__ float biasS[NUM_EXPERTS];
    __shared__ float redA[2][NUM_EXPERTS];
    __shared__ float sq[NUM_EXPERTS];
    __shared__ int   lastFlag;

    const uint32_t sb = smem_to_u32(sbuf);
    const int tid = threadIdx.x, lid = tid & 31, wid = tid >> 5;
    const int tg = lid & 7;              // token slot within half
    const int pg = lid >> 3;             // 0..3
    const int tokHalf = (wid & 1) * 32;  // token half
    const int pairBase = (wid >> 1) * 16 + pg;   // pairs pairBase + 4j
    const int tokBase = blockIdx.x * TM;

    if (tid < NUM_EXPERTS) biasS[tid] = bias[tid];

    auto issue = [&](int c) {
        const int st = c & 1;
        const int k0 = c * KC;
        const uint32_t ab = sb + st * A_STAGE_B;
        const uint32_t bb = sb + B_OFF + st * B_STAGE_B;
        // A: 64 rows x 4 x 16B units = 256 units, 2/thread
#pragma unroll
        for (int i = 0; i < 2; i++) {
            int unit = tid + 128 * i;
            int row = unit >> 2, off = unit & 3;
            CP_ASYNC16(ab + (uint32_t)(row * 80 + off * 16),
                       u + (size_t)(tokBase + row) * D_MODEL + k0 + off * 4);
        }
        // B: raw E rows k0..k0+15: 16 rows x 16 units = 256 units, 2/thread
#pragma unroll
        for (int i = 0; i < 2; i++) {
            int unit = tid + 128 * i;
            int kr = unit >> 4, off = unit & 15;
            CP_ASYNC16(bb + (uint32_t)(kr * 288 + off * 16),
                       E + (size_t)(k0 + kr) * NUM_EXPERTS + off * 4);
        }
        CP_COMMIT();
    };

    unsigned long long acc[4][4];
#pragma unroll
    for (int i = 0; i < 4; i++)
#pragma unroll
        for (int j = 0; j < 4; j++) acc[i][j] = 0ull;

    issue(0);
    issue(1);

    for (int c = 0; c < NCHUNK; c++) {
        if (c < NCHUNK - 1) CP_WAIT1(); else CP_WAIT0();
        __syncthreads();

        const int st = c & 1;
        const float* as = (const float*)(sbuf + st * A_STAGE_B);
        const unsigned long long* bs = (const unsigned long long*)(sbuf + B_OFF + st * B_STAGE_B);

#pragma unroll
        for (int k = 0; k < KC; k++) {
            unsigned long long av[4], bv[4];
#pragma unroll
            for (int i = 0; i < 4; i++)
                av[i] = dup2(as[(tokHalf + tg + 8 * i) * AWW + k]);
#pragma unroll
            for (int j = 0; j < 4; j++)
                bv[j] = bs[k * BWU + pairBase + 4 * j];
#pragma unroll
            for (int i = 0; i < 4; i++)
#pragma unroll
                for (int j = 0; j < 4; j++)
                    fma2(acc[i][j], av[i], bv[j]);
        }
        __syncthreads();
        if (c + 2 < NCHUNK) issue(c + 2);
    }

    // ---- epilogue: acc -> L[64][65] (overlays sbuf; 16640 <= 19456) ----
    float* L = (float*)sbuf;
#pragma unroll
    for (int i = 0; i < 4; i++) {
        const int t = tokHalf + tg + 8 * i;
#pragma unroll
        for (int j = 0; j < 4; j++) {
            const int e0 = 2 * (pairBase + 4 * j);
            float lo, hi;
            unpack2(acc[i][j], lo, hi);
            L[t * 65 + e0]     = lo;
            L[t * 65 + e0 + 1] = hi;
        }
    }
    __syncthreads();

    if (tid < TM) {
        const int t = tid;
        float p[64];
        float mx = -1e30f;
#pragma unroll
        for (int e = 0; e < 64; e++) { p[e] = L[t * 65 + e] + biasS[e]; mx = fmaxf(mx, p[e]); }
        float s = 0.f;
#pragma unroll
        for (int e = 0; e < 64; e++) { p[e] = expf(p[e] - mx); s += p[e]; }
        const float inv = 1.f / s;
#pragma unroll
        for (int e = 0; e < 64; e++) p[e] *= inv;

        const int gtok = tokBase + t;
        unsigned long long chosen = 0ull;
#pragma unroll
        for (int r = 0; r < TOP_K; r++) {
            float bv = -1.f; int bi = 0;
#pragma unroll
            for (int e = 0; e < 64; e++) {
                bool skip = (chosen >> e) & 1ull;
                if (!skip && p[e] > bv) { bv = p[e]; bi = e; }  // strict >: lowest idx ties
            }
            chosen |= 1ull << bi;
            out_idx[(size_t)gtok * TOP_K + r] = (float)bi;
            out_val[(size_t)gtok * TOP_K + r] = bv;
        }
#pragma unroll
        for (int e = 0; e < 64; e++) L[t * 65 + e] = p[e];
    }
    __syncthreads();

    // coalesced scores writeback: 4096 floats, 32/thread
#pragma unroll
    for (int i = 0; i < 32; i++) {
        int idx = tid + i * 128;
        int t = idx >> 6, e = idx & 63;
        out_scores[(size_t)(tokBase + t) * NUM_EXPERTS + e] = L[t * 65 + e];
    }
    // deterministic per-block expert sums
    if (tid < NUM_EXPERTS) {
        float s = 0.f;
#pragma unroll
        for (int t = 0; t < TM; t++) s += L[t * 65 + tid];
        g_expert_partial[(size_t)blockIdx.x * NUM_EXPERTS + tid] = s;
    }

    // ---- elected-last-CTA aux reduction (deterministic fixed-order sums) ----
    __threadfence();
    if (tid == 0) lastFlag = (atomicAdd(&g_done, 1) == NBLK - 1) ? 1 : 0;
    __syncthreads();
    if (lastFlag) {
        const int e = tid & 63, h = tid >> 6;      // 2 halves x 64 experts
        float s = 0.f;
        const int b0 = h * (NBLK / 2);
#pragma unroll 8
        for (int b = 0; b < NBLK / 2; b++)
            s += g_expert_partial[(size_t)(b0 + b) * NUM_EXPERTS + e];
        redA[h][e] = s;
        __syncthreads();
        if (tid < 64) {
            float m = (redA[0][tid] + redA[1][tid]) * (1.f / (float)N_TOKENS);
            sq[tid] = m * m;
        }
        __syncthreads();
        if (tid == 0) {
            float a = 0.f;
#pragma unroll
            for (int k = 0; k < 64; k++) a += sq[k];
            out_aux[0] = a * (float)NUM_EXPERTS;
            g_done = 0;                            // reset for next replay
        }
    }
}

extern "C" void kernel_launch(void* const* d_in, const int* in_sizes, int n_in,
                              void* d_out, int out_size)
{
    const float* u    = (const float*)d_in[0];
    const float* E    = (const float*)d_in[1];
    const float* bias = (const float*)d_in[2];

    float* out        = (float*)d_out;
    float* out_idx    = out;
    float* out_val    = out_idx + (size_t)N_TOKENS * TOP_K;
    float* out_scores = out_val + (size_t)N_TOKENS * TOP_K;
    float* out_aux    = out_scores + (size_t)N_TOKENS * NUM_EXPERTS;

    router_kernel<<<NBLK, 128>>>(u, E, bias, out_idx, out_val, out_scores, out_aux);
}